// round 2
// baseline (speedup 1.0000x reference)
#include <cuda_runtime.h>
#include <math.h>
#include <stdint.h>

#define Tn 524288
#define Bn 4096
#define Hn 512
#define EPS 1e-5f

// Scratch (device globals: no allocation allowed in kernel_launch)
__device__ float d_bow[(size_t)Bn * Hn];   // 8 MB
__device__ float d_z[(size_t)Bn * Hn];     // 8 MB
__device__ float d_mu[Hn];
__device__ float d_invstd[Hn];

// ---------------------------------------------------------------------------
__device__ __forceinline__ int lb(const int* __restrict__ a, int n, int key) {
    int lo = 0, hi = n;
    while (lo < hi) {
        int m = (lo + hi) >> 1;
        if (a[m] < key) lo = m + 1; else hi = m;
    }
    return lo;
}

// ---------------------------------------------------------------------------
// Kernel 1: embedding-bag (segment mean). One block per segment.
// 128 threads x float4 = one full emb row per token; 8 rows in flight.
// ---------------------------------------------------------------------------
__global__ __launch_bounds__(128)
void bag_kernel(const int* __restrict__ tokens,
                const int* __restrict__ seg,
                const float* __restrict__ emb) {
    int b = blockIdx.x;
    __shared__ int bounds[2];
    if (threadIdx.x < 2) bounds[threadIdx.x] = lb(seg, Tn, b + (int)threadIdx.x);
    __syncthreads();
    int start = bounds[0], end = bounds[1];

    int c = threadIdx.x;  // float4 index within row (0..127)
    float4 acc[8];
#pragma unroll
    for (int u = 0; u < 8; u++) acc[u] = make_float4(0.f, 0.f, 0.f, 0.f);

    int i = start;
    for (; i + 8 <= end; i += 8) {
        int tok[8];
#pragma unroll
        for (int u = 0; u < 8; u++) tok[u] = tokens[i + u];
        float4 v[8];
#pragma unroll
        for (int u = 0; u < 8; u++)
            v[u] = ((const float4*)(emb + (size_t)tok[u] * Hn))[c];
#pragma unroll
        for (int u = 0; u < 8; u++) {
            acc[u].x += v[u].x; acc[u].y += v[u].y;
            acc[u].z += v[u].z; acc[u].w += v[u].w;
        }
    }
    for (; i < end; i++) {
        int t0 = tokens[i];
        float4 v0 = ((const float4*)(emb + (size_t)t0 * Hn))[c];
        acc[0].x += v0.x; acc[0].y += v0.y; acc[0].z += v0.z; acc[0].w += v0.w;
    }

#pragma unroll
    for (int u = 4; u > 0; u >>= 1)
#pragma unroll
        for (int q = 0; q < u; q++) {
            acc[q].x += acc[q + u].x; acc[q].y += acc[q + u].y;
            acc[q].z += acc[q + u].z; acc[q].w += acc[q + u].w;
        }

    float inv = 1.0f / fmaxf((float)(end - start), 1.0f);
    float4 r;
    r.x = acc[0].x * inv; r.y = acc[0].y * inv;
    r.z = acc[0].z * inv; r.w = acc[0].w * inv;
    ((float4*)(d_bow + (size_t)b * Hn))[c] = r;
}

// ---------------------------------------------------------------------------
// Kernel 2: 3xTF32 tensor-core GEMM  z = bow * W1^T + b1
// CTA tile 128x64, BK=16, 256 threads (8 warps, warp tile 32x32).
// Each fp32 operand split into tf32 hi + tf32 lo; 3 MMAs per product term.
// ---------------------------------------------------------------------------
#define GM 128
#define GN 64
#define GK 16
#define LDA 20   // padded K-stride (floats); 20 keeps float4 alignment & conflict-free

__device__ __forceinline__ float tf32_rna(float x) {
    uint32_t u;
    asm("cvt.rna.tf32.f32 %0, %1;" : "=r"(u) : "f"(x));
    return __uint_as_float(u);
}

__device__ __forceinline__ void mma_tf32(float* c, const float* a, const float* b) {
    uint32_t const* A = reinterpret_cast<uint32_t const*>(a);
    uint32_t const* B = reinterpret_cast<uint32_t const*>(b);
    asm volatile(
        "mma.sync.aligned.m16n8k8.row.col.f32.tf32.tf32.f32 "
        "{%0,%1,%2,%3}, {%4,%5,%6,%7}, {%8,%9}, {%0,%1,%2,%3};"
        : "+f"(c[0]), "+f"(c[1]), "+f"(c[2]), "+f"(c[3])
        : "r"(A[0]), "r"(A[1]), "r"(A[2]), "r"(A[3]), "r"(B[0]), "r"(B[1]));
}

__global__ __launch_bounds__(256)
void gemm_kernel(const float* __restrict__ W1, const float* __restrict__ b1) {
    __shared__ float Ah[GM][LDA];
    __shared__ float Al[GM][LDA];
    __shared__ float Bh[GN][LDA];
    __shared__ float Bl[GN][LDA];

    int tid = threadIdx.x;
    int lane = tid & 31;
    int warp = tid >> 5;
    int wm = warp & 3;          // 0..3 -> warp row block (32 rows)
    int wn = warp >> 2;         // 0..1 -> warp col block (32 cols)
    int g = lane >> 2;          // 0..7
    int cc = lane & 3;          // 0..3

    int rowBase = blockIdx.x * GM;
    int colBase = blockIdx.y * GN;

    float acc[2][4][4];
#pragma unroll
    for (int mt = 0; mt < 2; mt++)
#pragma unroll
        for (int nt = 0; nt < 4; nt++)
#pragma unroll
            for (int q = 0; q < 4; q++) acc[mt][nt][q] = 0.f;

    for (int k0 = 0; k0 < Hn; k0 += GK) {
        // ---- stage A tile (128x16): 512 float4 -> 2 per thread ----
#pragma unroll
        for (int l = 0; l < 2; l++) {
            int f = l * 256 + tid;
            int r = f >> 2;
            int q = f & 3;
            float4 v = *(const float4*)(d_bow + (size_t)(rowBase + r) * Hn + k0 + q * 4);
            float4 h, lo;
            h.x = tf32_rna(v.x); lo.x = tf32_rna(v.x - h.x);
            h.y = tf32_rna(v.y); lo.y = tf32_rna(v.y - h.y);
            h.z = tf32_rna(v.z); lo.z = tf32_rna(v.z - h.z);
            h.w = tf32_rna(v.w); lo.w = tf32_rna(v.w - h.w);
            *(float4*)&Ah[r][q * 4] = h;
            *(float4*)&Al[r][q * 4] = lo;
        }
        // ---- stage B tile (64x16): 256 float4 -> 1 per thread ----
        {
            int r = tid >> 2;
            int q = tid & 3;
            float4 v = *(const float4*)(W1 + (size_t)(colBase + r) * Hn + k0 + q * 4);
            float4 h, lo;
            h.x = tf32_rna(v.x); lo.x = tf32_rna(v.x - h.x);
            h.y = tf32_rna(v.y); lo.y = tf32_rna(v.y - h.y);
            h.z = tf32_rna(v.z); lo.z = tf32_rna(v.z - h.z);
            h.w = tf32_rna(v.w); lo.w = tf32_rna(v.w - h.w);
            *(float4*)&Bh[r][q * 4] = h;
            *(float4*)&Bl[r][q * 4] = lo;
        }
        __syncthreads();

#pragma unroll
        for (int ks = 0; ks < 2; ks++) {
            int kb = ks * 8;
            float ah[2][4], al[2][4];
#pragma unroll
            for (int mt = 0; mt < 2; mt++) {
                int row = wm * 32 + mt * 16;
                ah[mt][0] = Ah[row + g][kb + cc];
                ah[mt][1] = Ah[row + g + 8][kb + cc];
                ah[mt][2] = Ah[row + g][kb + cc + 4];
                ah[mt][3] = Ah[row + g + 8][kb + cc + 4];
                al[mt][0] = Al[row + g][kb + cc];
                al[mt][1] = Al[row + g + 8][kb + cc];
                al[mt][2] = Al[row + g][kb + cc + 4];
                al[mt][3] = Al[row + g + 8][kb + cc + 4];
            }
            float bh[4][2], blo[4][2];
#pragma unroll
            for (int nt = 0; nt < 4; nt++) {
                int coln = wn * 32 + nt * 8 + g;
                bh[nt][0]  = Bh[coln][kb + cc];
                bh[nt][1]  = Bh[coln][kb + cc + 4];
                blo[nt][0] = Bl[coln][kb + cc];
                blo[nt][1] = Bl[coln][kb + cc + 4];
            }
#pragma unroll
            for (int mt = 0; mt < 2; mt++)
#pragma unroll
                for (int nt = 0; nt < 4; nt++) {
                    mma_tf32(acc[mt][nt], al[mt], bh[nt]);   // lo*hi
                    mma_tf32(acc[mt][nt], ah[mt], blo[nt]);  // hi*lo
                    mma_tf32(acc[mt][nt], ah[mt], bh[nt]);   // hi*hi (last: largest term)
                }
        }
        __syncthreads();
    }

    // ---- epilogue: bias + store ----
#pragma unroll
    for (int mt = 0; mt < 2; mt++) {
#pragma unroll
        for (int nt = 0; nt < 4; nt++) {
            int col = colBase + wn * 32 + nt * 8 + cc * 2;
            float b0 = b1[col], b1v = b1[col + 1];
            int row0 = rowBase + wm * 32 + mt * 16 + g;
            float2 o0, o1;
            o0.x = acc[mt][nt][0] + b0;
            o0.y = acc[mt][nt][1] + b1v;
            o1.x = acc[mt][nt][2] + b0;
            o1.y = acc[mt][nt][3] + b1v;
            *(float2*)(d_z + (size_t)row0 * Hn + col) = o0;
            *(float2*)(d_z + (size_t)(row0 + 8) * Hn + col) = o1;
        }
    }
}

// ---------------------------------------------------------------------------
// Kernel 3: per-column mean/invstd over B rows (deterministic).
// ---------------------------------------------------------------------------
__global__ void stats_kernel() {
    int tx = threadIdx.x;
    int ty = threadIdx.y;
    int col = blockIdx.x * 32 + tx;

    float s = 0.f, sq = 0.f;
    for (int i = ty; i < Bn; i += 8) {
        float v = d_z[(size_t)i * Hn + col];
        s += v;
        sq += v * v;
    }
    __shared__ float ss[8][32];
    __shared__ float ssq[8][32];
    ss[ty][tx] = s;
    ssq[ty][tx] = sq;
    __syncthreads();
    if (ty == 0) {
#pragma unroll
        for (int y = 1; y < 8; y++) { s += ss[y][tx]; sq += ssq[y][tx]; }
        float mu = s * (1.0f / Bn);
        float var = sq * (1.0f / Bn) - mu * mu;
        d_mu[col] = mu;
        d_invstd[col] = rsqrtf(var + EPS);
    }
}

// ---------------------------------------------------------------------------
// Kernel 4: normalize + ReLU + dot(w2) -> logits. One warp per row.
// ---------------------------------------------------------------------------
__global__ __launch_bounds__(256)
void logits_kernel(const float* __restrict__ gamma,
                   const float* __restrict__ beta,
                   const float* __restrict__ w2,
                   const float* __restrict__ b2,
                   float* __restrict__ out) {
    int warp = threadIdx.x >> 5;
    int lane = threadIdx.x & 31;
    int row = blockIdx.x * 8 + warp;

    const float4* zr = (const float4*)(d_z + (size_t)row * Hn);
    float sum = 0.f;
#pragma unroll
    for (int q = 0; q < 4; q++) {
        int c4 = lane + 32 * q;
        float4 z  = zr[c4];
        float4 mu = ((const float4*)d_mu)[c4];
        float4 is = ((const float4*)d_invstd)[c4];
        float4 g  = ((const float4*)gamma)[c4];
        float4 be = ((const float4*)beta)[c4];
        float4 w  = ((const float4*)w2)[c4];
        sum += fmaxf((z.x - mu.x) * is.x * g.x + be.x, 0.f) * w.x;
        sum += fmaxf((z.y - mu.y) * is.y * g.y + be.y, 0.f) * w.y;
        sum += fmaxf((z.z - mu.z) * is.z * g.z + be.z, 0.f) * w.z;
        sum += fmaxf((z.w - mu.w) * is.w * g.w + be.w, 0.f) * w.w;
    }
#pragma unroll
    for (int o = 16; o > 0; o >>= 1) sum += __shfl_xor_sync(0xFFFFFFFFu, sum, o);
    if (lane == 0) out[1 + row] = sum + b2[0];
}

// ---------------------------------------------------------------------------
// Kernel 5: BCEWithLogits mean loss over logits.
// ---------------------------------------------------------------------------
__global__ void loss_kernel(const float* __restrict__ t, float* __restrict__ out) {
    float acc = 0.f;
    for (int i = threadIdx.x; i < Bn; i += 1024) {
        float x = out[1 + i];
        float sp = fmaxf(x, 0.f) + log1pf(expf(-fabsf(x)));
        acc += sp - t[i] * x;
    }
    __shared__ float s[1024];
    s[threadIdx.x] = acc;
    __syncthreads();
    for (int st = 512; st > 0; st >>= 1) {
        if (threadIdx.x < st) s[threadIdx.x] += s[threadIdx.x + st];
        __syncthreads();
    }
    if (threadIdx.x == 0) out[0] = s[0] * (1.0f / Bn);
}

// ---------------------------------------------------------------------------
extern "C" void kernel_launch(void* const* d_in, const int* in_sizes, int n_in,
                              void* d_out, int out_size) {
    const int*   tokens = (const int*)d_in[0];
    const int*   seg    = (const int*)d_in[1];
    const float* t      = (const float*)d_in[2];
    const float* emb    = (const float*)d_in[3];
    const float* W1     = (const float*)d_in[4];
    const float* b1     = (const float*)d_in[5];
    const float* gamma  = (const float*)d_in[6];
    const float* beta   = (const float*)d_in[7];
    const float* w2     = (const float*)d_in[8];
    const float* b2     = (const float*)d_in[9];
    float* out = (float*)d_out;

    bag_kernel<<<Bn, 128>>>(tokens, seg, emb);
    gemm_kernel<<<dim3(Bn / GM, Hn / GN), 256>>>(W1, b1);
    stats_kernel<<<16, dim3(32, 8)>>>();
    logits_kernel<<<Bn / 8, 256>>>(gamma, beta, w2, b2, out);
    loss_kernel<<<1, 1024>>>(t, out);
}

// round 3
// speedup vs baseline: 1.2016x; 1.2016x over previous
#include <cuda_runtime.h>
#include <cuda_bf16.h>
#include <math.h>
#include <stdint.h>

#define Tn 524288
#define Bn 4096
#define Hn 512
#define EPS 1e-5f

// Scratch (device globals)
__device__ float d_bow[(size_t)Bn * Hn];   // 8 MB
__device__ float d_z[(size_t)Bn * Hn];     // 8 MB
__device__ float d_mu[Hn];
__device__ float d_invstd[Hn];
__device__ float d_ps[16][Hn];
__device__ float d_pq[16][Hn];

// ---------------------------------------------------------------------------
__device__ __forceinline__ int lb(const int* __restrict__ a, int n, int key) {
    int lo = 0, hi = n;
    while (lo < hi) {
        int m = (lo + hi) >> 1;
        if (a[m] < key) lo = m + 1; else hi = m;
    }
    return lo;
}

// ---------------------------------------------------------------------------
// Kernel 1: embedding-bag (segment mean). One block per segment.
// ---------------------------------------------------------------------------
__global__ __launch_bounds__(128)
void bag_kernel(const int* __restrict__ tokens,
                const int* __restrict__ seg,
                const float* __restrict__ emb) {
    int b = blockIdx.x;
    __shared__ int bounds[2];
    if (threadIdx.x < 2) bounds[threadIdx.x] = lb(seg, Tn, b + (int)threadIdx.x);
    __syncthreads();
    int start = bounds[0], end = bounds[1];

    int c = threadIdx.x;
    float4 acc[8];
#pragma unroll
    for (int u = 0; u < 8; u++) acc[u] = make_float4(0.f, 0.f, 0.f, 0.f);

    int i = start;
    for (; i + 8 <= end; i += 8) {
        int tok[8];
#pragma unroll
        for (int u = 0; u < 8; u++) tok[u] = tokens[i + u];
        float4 v[8];
#pragma unroll
        for (int u = 0; u < 8; u++)
            v[u] = ((const float4*)(emb + (size_t)tok[u] * Hn))[c];
#pragma unroll
        for (int u = 0; u < 8; u++) {
            acc[u].x += v[u].x; acc[u].y += v[u].y;
            acc[u].z += v[u].z; acc[u].w += v[u].w;
        }
    }
    for (; i < end; i++) {
        int t0 = tokens[i];
        float4 v0 = ((const float4*)(emb + (size_t)t0 * Hn))[c];
        acc[0].x += v0.x; acc[0].y += v0.y; acc[0].z += v0.z; acc[0].w += v0.w;
    }

#pragma unroll
    for (int u = 4; u > 0; u >>= 1)
#pragma unroll
        for (int q = 0; q < u; q++) {
            acc[q].x += acc[q + u].x; acc[q].y += acc[q + u].y;
            acc[q].z += acc[q + u].z; acc[q].w += acc[q + u].w;
        }

    float inv = 1.0f / fmaxf((float)(end - start), 1.0f);
    float4 r;
    r.x = acc[0].x * inv; r.y = acc[0].y * inv;
    r.z = acc[0].z * inv; r.w = acc[0].w * inv;
    ((float4*)(d_bow + (size_t)b * Hn))[c] = r;
}

// ---------------------------------------------------------------------------
// Kernel 2: bf16 split-K tensor-core GEMM  z = bow * W1^T + b1
// CTA tile 128x64, k-tile 32, 256 threads (8 warps 4x2, warp tile 32x32).
// A = Ah + Al (bf16 split); 3 MMAs: lo*hi, hi*lo, hi*hi. ldmatrix fragments.
// ---------------------------------------------------------------------------
#define GM 128
#define GN 64
#define KT 32
#define LDAS 40   // bf16 units; 80B row stride -> conflict-free ldmatrix

__device__ __forceinline__ void ldsm_x4(uint32_t* r, const __nv_bfloat16* p) {
    uint32_t addr = (uint32_t)__cvta_generic_to_shared(p);
    asm volatile("ldmatrix.sync.aligned.m8n8.x4.shared.b16 {%0,%1,%2,%3}, [%4];"
                 : "=r"(r[0]), "=r"(r[1]), "=r"(r[2]), "=r"(r[3]) : "r"(addr));
}

__device__ __forceinline__ void mma_bf16(float* c, const uint32_t* a, const uint32_t* b) {
    asm volatile(
        "mma.sync.aligned.m16n8k16.row.col.f32.bf16.bf16.f32 "
        "{%0,%1,%2,%3}, {%4,%5,%6,%7}, {%8,%9}, {%0,%1,%2,%3};"
        : "+f"(c[0]), "+f"(c[1]), "+f"(c[2]), "+f"(c[3])
        : "r"(a[0]), "r"(a[1]), "r"(a[2]), "r"(a[3]), "r"(b[0]), "r"(b[1]));
}

__global__ __launch_bounds__(256)
void gemm_kernel(const float* __restrict__ W1, const float* __restrict__ b1) {
    __shared__ __nv_bfloat16 Ah[GM][LDAS];
    __shared__ __nv_bfloat16 Al[GM][LDAS];
    __shared__ __nv_bfloat16 Bh[GN][LDAS];
    __shared__ __nv_bfloat16 Bl[GN][LDAS];

    int tid = threadIdx.x;
    int lane = tid & 31;
    int warp = tid >> 5;
    int wm = warp & 3;          // m block of 32
    int wn = warp >> 2;         // n block of 32
    int g = lane >> 2;          // 0..7
    int cc = lane & 3;          // 0..3
    int tile = lane >> 3;       // 0..3 (ldmatrix tile index)
    int rr = lane & 7;          // row within ldmatrix tile

    int rowBase = blockIdx.x * GM;
    int colBase = blockIdx.y * GN;

    float acc[2][4][4];
#pragma unroll
    for (int mt = 0; mt < 2; mt++)
#pragma unroll
        for (int nt = 0; nt < 4; nt++)
#pragma unroll
            for (int q = 0; q < 4; q++) acc[mt][nt][q] = 0.f;

    for (int k0 = 0; k0 < Hn; k0 += KT) {
        // ---- stage A tile (128x32 fp32 -> bf16 hi/lo): 4 float4 per thread ----
#pragma unroll
        for (int l = 0; l < 4; l++) {
            int f = l * 256 + tid;
            int r = f >> 3;          // 8 float4 per row
            int q = f & 7;
            float4 v = *(const float4*)(d_bow + (size_t)(rowBase + r) * Hn + k0 + q * 4);
            __nv_bfloat162 hxy = __floats2bfloat162_rn(v.x, v.y);
            __nv_bfloat162 hzw = __floats2bfloat162_rn(v.z, v.w);
            __nv_bfloat162 lxy = __floats2bfloat162_rn(v.x - __bfloat162float(hxy.x),
                                                       v.y - __bfloat162float(hxy.y));
            __nv_bfloat162 lzw = __floats2bfloat162_rn(v.z - __bfloat162float(hzw.x),
                                                       v.w - __bfloat162float(hzw.y));
            *(__nv_bfloat162*)&Ah[r][q * 4]     = hxy;
            *(__nv_bfloat162*)&Ah[r][q * 4 + 2] = hzw;
            *(__nv_bfloat162*)&Al[r][q * 4]     = lxy;
            *(__nv_bfloat162*)&Al[r][q * 4 + 2] = lzw;
        }
        // ---- stage B tile (64x32): 2 float4 per thread ----
#pragma unroll
        for (int l = 0; l < 2; l++) {
            int f = l * 256 + tid;
            int r = f >> 3;
            int q = f & 7;
            float4 v = *(const float4*)(W1 + (size_t)(colBase + r) * Hn + k0 + q * 4);
            __nv_bfloat162 hxy = __floats2bfloat162_rn(v.x, v.y);
            __nv_bfloat162 hzw = __floats2bfloat162_rn(v.z, v.w);
            __nv_bfloat162 lxy = __floats2bfloat162_rn(v.x - __bfloat162float(hxy.x),
                                                       v.y - __bfloat162float(hxy.y));
            __nv_bfloat162 lzw = __floats2bfloat162_rn(v.z - __bfloat162float(hzw.x),
                                                       v.w - __bfloat162float(hzw.y));
            *(__nv_bfloat162*)&Bh[r][q * 4]     = hxy;
            *(__nv_bfloat162*)&Bh[r][q * 4 + 2] = hzw;
            *(__nv_bfloat162*)&Bl[r][q * 4]     = lxy;
            *(__nv_bfloat162*)&Bl[r][q * 4 + 2] = lzw;
        }
        __syncthreads();

#pragma unroll
        for (int kk = 0; kk < 2; kk++) {
            int kb = kk * 16;
            // A fragments: tiles [m0-7,k0-7],[m8-15,k0-7],[m0-7,k8-15],[m8-15,k8-15]
            int ar_off = (tile & 1) * 8 + rr;
            int ak = kb + (tile >> 1) * 8;
            uint32_t afh[2][4], afl[2][4];
#pragma unroll
            for (int mt = 0; mt < 2; mt++) {
                int row = wm * 32 + mt * 16 + ar_off;
                ldsm_x4(afh[mt], &Ah[row][ak]);
                ldsm_x4(afl[mt], &Al[row][ak]);
            }
            // B fragments: x4 covers 16 n-cols -> 2 frags of n8.
            // tiles [n0-7,k0-7],[n0-7,k8-15],[n8-15,k0-7],[n8-15,k8-15]
            int br_off = (tile >> 1) * 8 + rr;
            int bk = kb + (tile & 1) * 8;
            uint32_t bfh[2][4], bfl[2][4];
#pragma unroll
            for (int np = 0; np < 2; np++) {
                int row = wn * 32 + np * 16 + br_off;
                ldsm_x4(bfh[np], &Bh[row][bk]);
                ldsm_x4(bfl[np], &Bl[row][bk]);
            }
#pragma unroll
            for (int mt = 0; mt < 2; mt++)
#pragma unroll
                for (int nt = 0; nt < 4; nt++) {
                    const uint32_t* bh = &bfh[nt >> 1][(nt & 1) * 2];
                    const uint32_t* bl = &bfl[nt >> 1][(nt & 1) * 2];
                    mma_bf16(acc[mt][nt], afl[mt], bh);  // lo*hi
                    mma_bf16(acc[mt][nt], afh[mt], bl);  // hi*lo
                    mma_bf16(acc[mt][nt], afh[mt], bh);  // hi*hi last
                }
        }
        __syncthreads();
    }

    // ---- epilogue: bias + store ----
#pragma unroll
    for (int mt = 0; mt < 2; mt++) {
#pragma unroll
        for (int nt = 0; nt < 4; nt++) {
            int col = colBase + wn * 32 + nt * 8 + cc * 2;
            float b0 = b1[col], b1v = b1[col + 1];
            int row0 = rowBase + wm * 32 + mt * 16 + g;
            float2 o0, o1;
            o0.x = acc[mt][nt][0] + b0;
            o0.y = acc[mt][nt][1] + b1v;
            o1.x = acc[mt][nt][2] + b0;
            o1.y = acc[mt][nt][3] + b1v;
            *(float2*)(d_z + (size_t)row0 * Hn + col) = o0;
            *(float2*)(d_z + (size_t)(row0 + 8) * Hn + col) = o1;
        }
    }
}

// ---------------------------------------------------------------------------
// Kernel 3a: partial column sums (256 blocks). Each block: 32 cols x 256 rows.
// ---------------------------------------------------------------------------
__global__ void stats1_kernel() {
    int tx = threadIdx.x;
    int ty = threadIdx.y;
    int col = blockIdx.x * 32 + tx;
    int rowBase = blockIdx.y * 256;

    float s = 0.f, sq = 0.f;
    for (int i = ty; i < 256; i += 8) {
        float v = d_z[(size_t)(rowBase + i) * Hn + col];
        s += v;
        sq += v * v;
    }
    __shared__ float ss[8][32];
    __shared__ float ssq[8][32];
    ss[ty][tx] = s;
    ssq[ty][tx] = sq;
    __syncthreads();
    if (ty == 0) {
#pragma unroll
        for (int y = 1; y < 8; y++) { s += ss[y][tx]; sq += ssq[y][tx]; }
        d_ps[blockIdx.y][col] = s;
        d_pq[blockIdx.y][col] = sq;
    }
}

// Kernel 3b: finalize mean/invstd
__global__ void stats2_kernel() {
    int col = blockIdx.x * blockDim.x + threadIdx.x;
    float s = 0.f, sq = 0.f;
#pragma unroll
    for (int y = 0; y < 16; y++) { s += d_ps[y][col]; sq += d_pq[y][col]; }
    float mu = s * (1.0f / Bn);
    float var = sq * (1.0f / Bn) - mu * mu;
    d_mu[col] = mu;
    d_invstd[col] = rsqrtf(var + EPS);
}

// ---------------------------------------------------------------------------
// Kernel 4: normalize + ReLU + dot(w2) -> logits. One warp per row.
// ---------------------------------------------------------------------------
__global__ __launch_bounds__(256)
void logits_kernel(const float* __restrict__ gamma,
                   const float* __restrict__ beta,
                   const float* __restrict__ w2,
                   const float* __restrict__ b2,
                   float* __restrict__ out) {
    int warp = threadIdx.x >> 5;
    int lane = threadIdx.x & 31;
    int row = blockIdx.x * 8 + warp;

    const float4* zr = (const float4*)(d_z + (size_t)row * Hn);
    float sum = 0.f;
#pragma unroll
    for (int q = 0; q < 4; q++) {
        int c4 = lane + 32 * q;
        float4 z  = zr[c4];
        float4 mu = ((const float4*)d_mu)[c4];
        float4 is = ((const float4*)d_invstd)[c4];
        float4 g  = ((const float4*)gamma)[c4];
        float4 be = ((const float4*)beta)[c4];
        float4 w  = ((const float4*)w2)[c4];
        sum += fmaxf((z.x - mu.x) * is.x * g.x + be.x, 0.f) * w.x;
        sum += fmaxf((z.y - mu.y) * is.y * g.y + be.y, 0.f) * w.y;
        sum += fmaxf((z.z - mu.z) * is.z * g.z + be.z, 0.f) * w.z;
        sum += fmaxf((z.w - mu.w) * is.w * g.w + be.w, 0.f) * w.w;
    }
#pragma unroll
    for (int o = 16; o > 0; o >>= 1) sum += __shfl_xor_sync(0xFFFFFFFFu, sum, o);
    if (lane == 0) out[1 + row] = sum + b2[0];
}

// ---------------------------------------------------------------------------
// Kernel 5: BCEWithLogits mean loss.
// ---------------------------------------------------------------------------
__global__ void loss_kernel(const float* __restrict__ t, float* __restrict__ out) {
    float acc = 0.f;
    for (int i = threadIdx.x; i < Bn; i += 1024) {
        float x = out[1 + i];
        float sp = fmaxf(x, 0.f) + log1pf(expf(-fabsf(x)));
        acc += sp - t[i] * x;
    }
    __shared__ float s[1024];
    s[threadIdx.x] = acc;
    __syncthreads();
    for (int st = 512; st > 0; st >>= 1) {
        if (threadIdx.x < st) s[threadIdx.x] += s[threadIdx.x + st];
        __syncthreads();
    }
    if (threadIdx.x == 0) out[0] = s[0] * (1.0f / Bn);
}

// ---------------------------------------------------------------------------
extern "C" void kernel_launch(void* const* d_in, const int* in_sizes, int n_in,
                              void* d_out, int out_size) {
    const int*   tokens = (const int*)d_in[0];
    const int*   seg    = (const int*)d_in[1];
    const float* t      = (const float*)d_in[2];
    const float* emb    = (const float*)d_in[3];
    const float* W1     = (const float*)d_in[4];
    const float* b1     = (const float*)d_in[5];
    const float* gamma  = (const float*)d_in[6];
    const float* beta   = (const float*)d_in[7];
    const float* w2     = (const float*)d_in[8];
    const float* b2     = (const float*)d_in[9];
    float* out = (float*)d_out;

    bag_kernel<<<Bn, 128>>>(tokens, seg, emb);
    gemm_kernel<<<dim3(Bn / GM, Hn / GN), 256>>>(W1, b1);
    stats1_kernel<<<dim3(16, 16), dim3(32, 8)>>>();
    stats2_kernel<<<2, 256>>>();
    logits_kernel<<<Bn / 8, 256>>>(gamma, beta, w2, b2, out);
    loss_kernel<<<1, 1024>>>(t, out);
}

// round 4
// speedup vs baseline: 1.4234x; 1.1846x over previous
#include <cuda_runtime.h>
#include <cuda_bf16.h>
#include <math.h>
#include <stdint.h>

#define Tn 524288
#define Bn 4096
#define Hn 512
#define EPS 1e-5f

// Scratch (device globals)
__device__ float d_bow[(size_t)Bn * Hn];   // 8 MB
__device__ float d_z[(size_t)Bn * Hn];     // 8 MB
__device__ float d_ps[16][Hn];
__device__ float d_pq[16][Hn];
__device__ int   d_segstart[Bn + 1];

// ---------------------------------------------------------------------------
// Kernel 0: segment boundary detect (seg_ids sorted). Handles empty segments.
// ---------------------------------------------------------------------------
__global__ __launch_bounds__(256)
void bounds_kernel(const int* __restrict__ seg) {
    int i = blockIdx.x * 256 + threadIdx.x;
    if (i >= Tn) return;
    int cur = seg[i];
    int prev = (i == 0) ? -1 : seg[i - 1];
    for (int b = prev + 1; b <= cur; b++) d_segstart[b] = i;
    if (i == Tn - 1)
        for (int b = cur + 1; b <= Bn; b++) d_segstart[b] = Tn;
}

// ---------------------------------------------------------------------------
// Kernel 1: embedding-bag (segment mean). One block per segment.
// Fully predicated 8-wide main loop: tail keeps 8 loads in flight.
// ---------------------------------------------------------------------------
__global__ __launch_bounds__(128)
void bag_kernel(const int* __restrict__ tokens,
                const float* __restrict__ emb) {
    int b = blockIdx.x;
    int start = d_segstart[b];
    int end   = d_segstart[b + 1];

    int c = threadIdx.x;  // float4 index within row (0..127)
    float4 acc[4];
#pragma unroll
    for (int u = 0; u < 4; u++) acc[u] = make_float4(0.f, 0.f, 0.f, 0.f);

    for (int i = start; i < end; i += 8) {
        int rem = end - i;   // >= 1
        int tok[8];
        float w[8];
#pragma unroll
        for (int u = 0; u < 8; u++) {
            bool ok = (u < rem);
            tok[u] = tokens[ok ? (i + u) : i];
            w[u] = ok ? 1.0f : 0.0f;
        }
        float4 v[8];
#pragma unroll
        for (int u = 0; u < 8; u++)
            v[u] = ((const float4*)(emb + (size_t)tok[u] * Hn))[c];
#pragma unroll
        for (int u = 0; u < 8; u++) {
            float4& a = acc[u & 3];
            a.x = fmaf(v[u].x, w[u], a.x);
            a.y = fmaf(v[u].y, w[u], a.y);
            a.z = fmaf(v[u].z, w[u], a.z);
            a.w = fmaf(v[u].w, w[u], a.w);
        }
    }

#pragma unroll
    for (int u = 2; u > 0; u >>= 1)
#pragma unroll
        for (int q = 0; q < u; q++) {
            acc[q].x += acc[q + u].x; acc[q].y += acc[q + u].y;
            acc[q].z += acc[q + u].z; acc[q].w += acc[q + u].w;
        }

    float inv = 1.0f / fmaxf((float)(end - start), 1.0f);
    float4 r;
    r.x = acc[0].x * inv; r.y = acc[0].y * inv;
    r.z = acc[0].z * inv; r.w = acc[0].w * inv;
    ((float4*)(d_bow + (size_t)b * Hn))[c] = r;
}

// ---------------------------------------------------------------------------
// Kernel 2: bf16 split tensor-core GEMM  z = bow * W1^T + b1
// CTA tile 128x64, k-tile 32, 256 threads (8 warps 4x2, warp tile 32x32).
// ---------------------------------------------------------------------------
#define GM 128
#define GN 64
#define KT 32
#define LDAS 40   // bf16 units; 80B row stride -> conflict-free ldmatrix

__device__ __forceinline__ void ldsm_x4(uint32_t* r, const __nv_bfloat16* p) {
    uint32_t addr = (uint32_t)__cvta_generic_to_shared(p);
    asm volatile("ldmatrix.sync.aligned.m8n8.x4.shared.b16 {%0,%1,%2,%3}, [%4];"
                 : "=r"(r[0]), "=r"(r[1]), "=r"(r[2]), "=r"(r[3]) : "r"(addr));
}

__device__ __forceinline__ void mma_bf16(float* c, const uint32_t* a, const uint32_t* b) {
    asm volatile(
        "mma.sync.aligned.m16n8k16.row.col.f32.bf16.bf16.f32 "
        "{%0,%1,%2,%3}, {%4,%5,%6,%7}, {%8,%9}, {%0,%1,%2,%3};"
        : "+f"(c[0]), "+f"(c[1]), "+f"(c[2]), "+f"(c[3])
        : "r"(a[0]), "r"(a[1]), "r"(a[2]), "r"(a[3]), "r"(b[0]), "r"(b[1]));
}

__global__ __launch_bounds__(256)
void gemm_kernel(const float* __restrict__ W1, const float* __restrict__ b1) {
    __shared__ __nv_bfloat16 Ah[GM][LDAS];
    __shared__ __nv_bfloat16 Al[GM][LDAS];
    __shared__ __nv_bfloat16 Bh[GN][LDAS];
    __shared__ __nv_bfloat16 Bl[GN][LDAS];

    int tid = threadIdx.x;
    int lane = tid & 31;
    int warp = tid >> 5;
    int wm = warp & 3;
    int wn = warp >> 2;
    int g = lane >> 2;
    int cc = lane & 3;
    int tile = lane >> 3;
    int rr = lane & 7;

    int rowBase = blockIdx.x * GM;
    int colBase = blockIdx.y * GN;

    float acc[2][4][4];
#pragma unroll
    for (int mt = 0; mt < 2; mt++)
#pragma unroll
        for (int nt = 0; nt < 4; nt++)
#pragma unroll
            for (int q = 0; q < 4; q++) acc[mt][nt][q] = 0.f;

    for (int k0 = 0; k0 < Hn; k0 += KT) {
#pragma unroll
        for (int l = 0; l < 4; l++) {
            int f = l * 256 + tid;
            int r = f >> 3;
            int q = f & 7;
            float4 v = *(const float4*)(d_bow + (size_t)(rowBase + r) * Hn + k0 + q * 4);
            __nv_bfloat162 hxy = __floats2bfloat162_rn(v.x, v.y);
            __nv_bfloat162 hzw = __floats2bfloat162_rn(v.z, v.w);
            __nv_bfloat162 lxy = __floats2bfloat162_rn(v.x - __bfloat162float(hxy.x),
                                                       v.y - __bfloat162float(hxy.y));
            __nv_bfloat162 lzw = __floats2bfloat162_rn(v.z - __bfloat162float(hzw.x),
                                                       v.w - __bfloat162float(hzw.y));
            *(__nv_bfloat162*)&Ah[r][q * 4]     = hxy;
            *(__nv_bfloat162*)&Ah[r][q * 4 + 2] = hzw;
            *(__nv_bfloat162*)&Al[r][q * 4]     = lxy;
            *(__nv_bfloat162*)&Al[r][q * 4 + 2] = lzw;
        }
#pragma unroll
        for (int l = 0; l < 2; l++) {
            int f = l * 256 + tid;
            int r = f >> 3;
            int q = f & 7;
            float4 v = *(const float4*)(W1 + (size_t)(colBase + r) * Hn + k0 + q * 4);
            __nv_bfloat162 hxy = __floats2bfloat162_rn(v.x, v.y);
            __nv_bfloat162 hzw = __floats2bfloat162_rn(v.z, v.w);
            __nv_bfloat162 lxy = __floats2bfloat162_rn(v.x - __bfloat162float(hxy.x),
                                                       v.y - __bfloat162float(hxy.y));
            __nv_bfloat162 lzw = __floats2bfloat162_rn(v.z - __bfloat162float(hzw.x),
                                                       v.w - __bfloat162float(hzw.y));
            *(__nv_bfloat162*)&Bh[r][q * 4]     = hxy;
            *(__nv_bfloat162*)&Bh[r][q * 4 + 2] = hzw;
            *(__nv_bfloat162*)&Bl[r][q * 4]     = lxy;
            *(__nv_bfloat162*)&Bl[r][q * 4 + 2] = lzw;
        }
        __syncthreads();

#pragma unroll
        for (int kk = 0; kk < 2; kk++) {
            int kb = kk * 16;
            int ar_off = (tile & 1) * 8 + rr;
            int ak = kb + (tile >> 1) * 8;
            uint32_t afh[2][4], afl[2][4];
#pragma unroll
            for (int mt = 0; mt < 2; mt++) {
                int row = wm * 32 + mt * 16 + ar_off;
                ldsm_x4(afh[mt], &Ah[row][ak]);
                ldsm_x4(afl[mt], &Al[row][ak]);
            }
            int br_off = (tile >> 1) * 8 + rr;
            int bk = kb + (tile & 1) * 8;
            uint32_t bfh[2][4], bfl[2][4];
#pragma unroll
            for (int np = 0; np < 2; np++) {
                int row = wn * 32 + np * 16 + br_off;
                ldsm_x4(bfh[np], &Bh[row][bk]);
                ldsm_x4(bfl[np], &Bl[row][bk]);
            }
#pragma unroll
            for (int mt = 0; mt < 2; mt++)
#pragma unroll
                for (int nt = 0; nt < 4; nt++) {
                    const uint32_t* bh = &bfh[nt >> 1][(nt & 1) * 2];
                    const uint32_t* bl = &bfl[nt >> 1][(nt & 1) * 2];
                    mma_bf16(acc[mt][nt], afl[mt], bh);
                    mma_bf16(acc[mt][nt], afh[mt], bl);
                    mma_bf16(acc[mt][nt], afh[mt], bh);
                }
        }
        __syncthreads();
    }

#pragma unroll
    for (int mt = 0; mt < 2; mt++) {
#pragma unroll
        for (int nt = 0; nt < 4; nt++) {
            int col = colBase + wn * 32 + nt * 8 + cc * 2;
            float b0 = b1[col], b1v = b1[col + 1];
            int row0 = rowBase + wm * 32 + mt * 16 + g;
            float2 o0, o1;
            o0.x = acc[mt][nt][0] + b0;
            o0.y = acc[mt][nt][1] + b1v;
            o1.x = acc[mt][nt][2] + b0;
            o1.y = acc[mt][nt][3] + b1v;
            *(float2*)(d_z + (size_t)row0 * Hn + col) = o0;
            *(float2*)(d_z + (size_t)(row0 + 8) * Hn + col) = o1;
        }
    }
}

// ---------------------------------------------------------------------------
// Kernel 3: partial column sums (256 blocks). Each block: 32 cols x 256 rows.
// ---------------------------------------------------------------------------
__global__ void stats1_kernel() {
    int tx = threadIdx.x;
    int ty = threadIdx.y;
    int col = blockIdx.x * 32 + tx;
    int rowBase = blockIdx.y * 256;

    float s = 0.f, sq = 0.f;
    for (int i = ty; i < 256; i += 8) {
        float v = d_z[(size_t)(rowBase + i) * Hn + col];
        s += v;
        sq += v * v;
    }
    __shared__ float ss[8][32];
    __shared__ float ssq[8][32];
    ss[ty][tx] = s;
    ssq[ty][tx] = sq;
    __syncthreads();
    if (ty == 0) {
#pragma unroll
        for (int y = 1; y < 8; y++) { s += ss[y][tx]; sq += ssq[y][tx]; }
        d_ps[blockIdx.y][col] = s;
        d_pq[blockIdx.y][col] = sq;
    }
}

// ---------------------------------------------------------------------------
// Kernel 4: finalize stats (in smem) + normalize + ReLU + dot(w2) -> logits.
// 128 blocks x 256 threads; each block: 32 rows (8 warps x 4 rows).
// ---------------------------------------------------------------------------
__global__ __launch_bounds__(256)
void logits_kernel(const float* __restrict__ gamma,
                   const float* __restrict__ beta,
                   const float* __restrict__ w2,
                   const float* __restrict__ b2,
                   float* __restrict__ out) {
    __shared__ float smu[Hn];
    __shared__ float sA[Hn];   // invstd * gamma

    int tid = threadIdx.x;
#pragma unroll
    for (int c = tid; c < Hn; c += 256) {
        float s = 0.f, sq = 0.f;
#pragma unroll
        for (int y = 0; y < 16; y++) { s += d_ps[y][c]; sq += d_pq[y][c]; }
        float mu = s * (1.0f / Bn);
        float var = sq * (1.0f / Bn) - mu * mu;
        smu[c] = mu;
        sA[c] = rsqrtf(var + EPS) * gamma[c];
    }
    __syncthreads();

    int warp = tid >> 5;
    int lane = tid & 31;
    float bias2 = b2[0];

#pragma unroll
    for (int r4 = 0; r4 < 4; r4++) {
        int row = blockIdx.x * 32 + warp * 4 + r4;
        const float4* zr = (const float4*)(d_z + (size_t)row * Hn);
        float sum = 0.f;
#pragma unroll
        for (int q = 0; q < 4; q++) {
            int c4 = lane + 32 * q;
            float4 z  = zr[c4];
            float4 mu = ((const float4*)smu)[c4];
            float4 a  = ((const float4*)sA)[c4];
            float4 be = ((const float4*)beta)[c4];
            float4 w  = ((const float4*)w2)[c4];
            sum += fmaxf((z.x - mu.x) * a.x + be.x, 0.f) * w.x;
            sum += fmaxf((z.y - mu.y) * a.y + be.y, 0.f) * w.y;
            sum += fmaxf((z.z - mu.z) * a.z + be.z, 0.f) * w.z;
            sum += fmaxf((z.w - mu.w) * a.w + be.w, 0.f) * w.w;
        }
#pragma unroll
        for (int o = 16; o > 0; o >>= 1) sum += __shfl_xor_sync(0xFFFFFFFFu, sum, o);
        if (lane == 0) out[1 + row] = sum + bias2;
    }
}

// ---------------------------------------------------------------------------
// Kernel 5: BCEWithLogits mean loss.
// ---------------------------------------------------------------------------
__global__ void loss_kernel(const float* __restrict__ t, float* __restrict__ out) {
    float acc = 0.f;
    for (int i = threadIdx.x; i < Bn; i += 1024) {
        float x = out[1 + i];
        float sp = fmaxf(x, 0.f) + log1pf(expf(-fabsf(x)));
        acc += sp - t[i] * x;
    }
    __shared__ float s[1024];
    s[threadIdx.x] = acc;
    __syncthreads();
    for (int st = 512; st > 0; st >>= 1) {
        if (threadIdx.x < st) s[threadIdx.x] += s[threadIdx.x + st];
        __syncthreads();
    }
    if (threadIdx.x == 0) out[0] = s[0] * (1.0f / Bn);
}

// ---------------------------------------------------------------------------
extern "C" void kernel_launch(void* const* d_in, const int* in_sizes, int n_in,
                              void* d_out, int out_size) {
    const int*   tokens = (const int*)d_in[0];
    const int*   seg    = (const int*)d_in[1];
    const float* t      = (const float*)d_in[2];
    const float* emb    = (const float*)d_in[3];
    const float* W1     = (const float*)d_in[4];
    const float* b1     = (const float*)d_in[5];
    const float* gamma  = (const float*)d_in[6];
    const float* beta   = (const float*)d_in[7];
    const float* w2     = (const float*)d_in[8];
    const float* b2     = (const float*)d_in[9];
    float* out = (float*)d_out;

    bounds_kernel<<<(Tn + 255) / 256, 256>>>(seg);
    bag_kernel<<<Bn, 128>>>(tokens, emb);
    gemm_kernel<<<dim3(Bn / GM, Hn / GN), 256>>>(W1, b1);
    stats1_kernel<<<dim3(16, 16), dim3(32, 8)>>>();
    logits_kernel<<<128, 256>>>(gamma, beta, w2, b2, out);
    loss_kernel<<<1, 1024>>>(t, out);
}

// round 5
// speedup vs baseline: 1.4839x; 1.0425x over previous
#include <cuda_runtime.h>
#include <cuda_bf16.h>
#include <math.h>
#include <stdint.h>

#define Tn 524288
#define Bn 4096
#define Hn 512
#define EPS 1e-5f

// Scratch (device globals)
__device__ float d_bow[(size_t)Bn * Hn];   // 8 MB
__device__ float d_z[(size_t)Bn * Hn];     // 8 MB
__device__ float d_ps[32][Hn];             // per-GEMM-CTA-rowblock column sums
__device__ float d_pq[32][Hn];             // per-GEMM-CTA-rowblock column sumsq
__device__ int   d_segstart[Bn + 1];

// ---------------------------------------------------------------------------
// Kernel 0: segment boundary detect (seg_ids sorted). Handles empty segments.
// ---------------------------------------------------------------------------
__global__ __launch_bounds__(256)
void bounds_kernel(const int* __restrict__ seg) {
    int i = blockIdx.x * 256 + threadIdx.x;
    if (i >= Tn) return;
    int cur = seg[i];
    int prev = (i == 0) ? -1 : seg[i - 1];
    for (int b = prev + 1; b <= cur; b++) d_segstart[b] = i;
    if (i == Tn - 1)
        for (int b = cur + 1; b <= Bn; b++) d_segstart[b] = Tn;
}

// ---------------------------------------------------------------------------
// Kernel 1: embedding-bag (segment mean). One block per segment.
// Fully predicated 8-wide main loop: tail keeps 8 loads in flight.
// ---------------------------------------------------------------------------
__global__ __launch_bounds__(128)
void bag_kernel(const int* __restrict__ tokens,
                const float* __restrict__ emb) {
    int b = blockIdx.x;
    int start = d_segstart[b];
    int end   = d_segstart[b + 1];

    int c = threadIdx.x;
    float4 acc[4];
#pragma unroll
    for (int u = 0; u < 4; u++) acc[u] = make_float4(0.f, 0.f, 0.f, 0.f);

    for (int i = start; i < end; i += 8) {
        int rem = end - i;   // >= 1
        int tok[8];
        float w[8];
#pragma unroll
        for (int u = 0; u < 8; u++) {
            bool ok = (u < rem);
            tok[u] = tokens[ok ? (i + u) : i];
            w[u] = ok ? 1.0f : 0.0f;
        }
        float4 v[8];
#pragma unroll
        for (int u = 0; u < 8; u++)
            v[u] = ((const float4*)(emb + (size_t)tok[u] * Hn))[c];
#pragma unroll
        for (int u = 0; u < 8; u++) {
            float4& a = acc[u & 3];
            a.x = fmaf(v[u].x, w[u], a.x);
            a.y = fmaf(v[u].y, w[u], a.y);
            a.z = fmaf(v[u].z, w[u], a.z);
            a.w = fmaf(v[u].w, w[u], a.w);
        }
    }

#pragma unroll
    for (int u = 2; u > 0; u >>= 1)
#pragma unroll
        for (int q = 0; q < u; q++) {
            acc[q].x += acc[q + u].x; acc[q].y += acc[q + u].y;
            acc[q].z += acc[q + u].z; acc[q].w += acc[q + u].w;
        }

    float inv = 1.0f / fmaxf((float)(end - start), 1.0f);
    float4 r;
    r.x = acc[0].x * inv; r.y = acc[0].y * inv;
    r.z = acc[0].z * inv; r.w = acc[0].w * inv;
    ((float4*)(d_bow + (size_t)b * Hn))[c] = r;
}

// ---------------------------------------------------------------------------
// Kernel 2: bf16 split tensor-core GEMM  z = bow * W1^T + b1,
// with fused per-CTA column-stat partials (sum, sumsq over the CTA's 128 rows).
// CTA tile 128x64, k-tile 32, 256 threads (8 warps 4x2, warp tile 32x32).
// ---------------------------------------------------------------------------
#define GM 128
#define GN 64
#define KT 32
#define LDAS 40   // bf16 units; 80B row stride -> conflict-free ldmatrix

__device__ __forceinline__ void ldsm_x4(uint32_t* r, const __nv_bfloat16* p) {
    uint32_t addr = (uint32_t)__cvta_generic_to_shared(p);
    asm volatile("ldmatrix.sync.aligned.m8n8.x4.shared.b16 {%0,%1,%2,%3}, [%4];"
                 : "=r"(r[0]), "=r"(r[1]), "=r"(r[2]), "=r"(r[3]) : "r"(addr));
}

__device__ __forceinline__ void mma_bf16(float* c, const uint32_t* a, const uint32_t* b) {
    asm volatile(
        "mma.sync.aligned.m16n8k16.row.col.f32.bf16.bf16.f32 "
        "{%0,%1,%2,%3}, {%4,%5,%6,%7}, {%8,%9}, {%0,%1,%2,%3};"
        : "+f"(c[0]), "+f"(c[1]), "+f"(c[2]), "+f"(c[3])
        : "r"(a[0]), "r"(a[1]), "r"(a[2]), "r"(a[3]), "r"(b[0]), "r"(b[1]));
}

__global__ __launch_bounds__(256)
void gemm_kernel(const float* __restrict__ W1, const float* __restrict__ b1) {
    __shared__ __nv_bfloat16 Ah[GM][LDAS];
    __shared__ __nv_bfloat16 Al[GM][LDAS];
    __shared__ __nv_bfloat16 Bh[GN][LDAS];
    __shared__ __nv_bfloat16 Bl[GN][LDAS];
    __shared__ float sS[2][4][32];   // [wn][wm][col-within-32]
    __shared__ float sQ[2][4][32];

    int tid = threadIdx.x;
    int lane = tid & 31;
    int warp = tid >> 5;
    int wm = warp & 3;
    int wn = warp >> 2;
    int g = lane >> 2;
    int cc = lane & 3;
    int tile = lane >> 3;
    int rr = lane & 7;

    int rowBase = blockIdx.x * GM;
    int colBase = blockIdx.y * GN;

    float acc[2][4][4];
#pragma unroll
    for (int mt = 0; mt < 2; mt++)
#pragma unroll
        for (int nt = 0; nt < 4; nt++)
#pragma unroll
            for (int q = 0; q < 4; q++) acc[mt][nt][q] = 0.f;

    for (int k0 = 0; k0 < Hn; k0 += KT) {
#pragma unroll
        for (int l = 0; l < 4; l++) {
            int f = l * 256 + tid;
            int r = f >> 3;
            int q = f & 7;
            float4 v = *(const float4*)(d_bow + (size_t)(rowBase + r) * Hn + k0 + q * 4);
            __nv_bfloat162 hxy = __floats2bfloat162_rn(v.x, v.y);
            __nv_bfloat162 hzw = __floats2bfloat162_rn(v.z, v.w);
            __nv_bfloat162 lxy = __floats2bfloat162_rn(v.x - __bfloat162float(hxy.x),
                                                       v.y - __bfloat162float(hxy.y));
            __nv_bfloat162 lzw = __floats2bfloat162_rn(v.z - __bfloat162float(hzw.x),
                                                       v.w - __bfloat162float(hzw.y));
            *(__nv_bfloat162*)&Ah[r][q * 4]     = hxy;
            *(__nv_bfloat162*)&Ah[r][q * 4 + 2] = hzw;
            *(__nv_bfloat162*)&Al[r][q * 4]     = lxy;
            *(__nv_bfloat162*)&Al[r][q * 4 + 2] = lzw;
        }
#pragma unroll
        for (int l = 0; l < 2; l++) {
            int f = l * 256 + tid;
            int r = f >> 3;
            int q = f & 7;
            float4 v = *(const float4*)(W1 + (size_t)(colBase + r) * Hn + k0 + q * 4);
            __nv_bfloat162 hxy = __floats2bfloat162_rn(v.x, v.y);
            __nv_bfloat162 hzw = __floats2bfloat162_rn(v.z, v.w);
            __nv_bfloat162 lxy = __floats2bfloat162_rn(v.x - __bfloat162float(hxy.x),
                                                       v.y - __bfloat162float(hxy.y));
            __nv_bfloat162 lzw = __floats2bfloat162_rn(v.z - __bfloat162float(hzw.x),
                                                       v.w - __bfloat162float(hzw.y));
            *(__nv_bfloat162*)&Bh[r][q * 4]     = hxy;
            *(__nv_bfloat162*)&Bh[r][q * 4 + 2] = hzw;
            *(__nv_bfloat162*)&Bl[r][q * 4]     = lxy;
            *(__nv_bfloat162*)&Bl[r][q * 4 + 2] = lzw;
        }
        __syncthreads();

#pragma unroll
        for (int kk = 0; kk < 2; kk++) {
            int kb = kk * 16;
            int ar_off = (tile & 1) * 8 + rr;
            int ak = kb + (tile >> 1) * 8;
            uint32_t afh[2][4], afl[2][4];
#pragma unroll
            for (int mt = 0; mt < 2; mt++) {
                int row = wm * 32 + mt * 16 + ar_off;
                ldsm_x4(afh[mt], &Ah[row][ak]);
                ldsm_x4(afl[mt], &Al[row][ak]);
            }
            int br_off = (tile >> 1) * 8 + rr;
            int bk = kb + (tile & 1) * 8;
            uint32_t bfh[2][4], bfl[2][4];
#pragma unroll
            for (int np = 0; np < 2; np++) {
                int row = wn * 32 + np * 16 + br_off;
                ldsm_x4(bfh[np], &Bh[row][bk]);
                ldsm_x4(bfl[np], &Bl[row][bk]);
            }
#pragma unroll
            for (int mt = 0; mt < 2; mt++)
#pragma unroll
                for (int nt = 0; nt < 4; nt++) {
                    const uint32_t* bh = &bfh[nt >> 1][(nt & 1) * 2];
                    const uint32_t* bl = &bfl[nt >> 1][(nt & 1) * 2];
                    mma_bf16(acc[mt][nt], afl[mt], bh);
                    mma_bf16(acc[mt][nt], afh[mt], bl);
                    mma_bf16(acc[mt][nt], afh[mt], bh);
                }
        }
        __syncthreads();
    }

    // ---- epilogue: bias + store z + fused column-stat partials ----
    float colS[4][2];   // [nt][col parity] sum over this thread's 4 rows
    float colQ[4][2];
#pragma unroll
    for (int nt = 0; nt < 4; nt++)
        colS[nt][0] = colS[nt][1] = colQ[nt][0] = colQ[nt][1] = 0.f;

#pragma unroll
    for (int mt = 0; mt < 2; mt++) {
#pragma unroll
        for (int nt = 0; nt < 4; nt++) {
            int col = colBase + wn * 32 + nt * 8 + cc * 2;
            float b0 = b1[col], b1v = b1[col + 1];
            int row0 = rowBase + wm * 32 + mt * 16 + g;
            float2 o0, o1;
            o0.x = acc[mt][nt][0] + b0;
            o0.y = acc[mt][nt][1] + b1v;
            o1.x = acc[mt][nt][2] + b0;
            o1.y = acc[mt][nt][3] + b1v;
            *(float2*)(d_z + (size_t)row0 * Hn + col) = o0;
            *(float2*)(d_z + (size_t)(row0 + 8) * Hn + col) = o1;
            colS[nt][0] += o0.x + o1.x;
            colS[nt][1] += o0.y + o1.y;
            colQ[nt][0] += o0.x * o0.x + o1.x * o1.x;
            colQ[nt][1] += o0.y * o0.y + o1.y * o1.y;
        }
    }
    // reduce over g (lanes sharing cc): xor offsets 4, 8, 16
#pragma unroll
    for (int o = 4; o <= 16; o <<= 1) {
#pragma unroll
        for (int nt = 0; nt < 4; nt++) {
#pragma unroll
            for (int p = 0; p < 2; p++) {
                colS[nt][p] += __shfl_xor_sync(0xFFFFFFFFu, colS[nt][p], o);
                colQ[nt][p] += __shfl_xor_sync(0xFFFFFFFFu, colQ[nt][p], o);
            }
        }
    }
    if (g == 0) {   // lanes 0..3
#pragma unroll
        for (int nt = 0; nt < 4; nt++) {
#pragma unroll
            for (int p = 0; p < 2; p++) {
                sS[wn][wm][nt * 8 + cc * 2 + p] = colS[nt][p];
                sQ[wn][wm][nt * 8 + cc * 2 + p] = colQ[nt][p];
            }
        }
    }
    __syncthreads();
    if (tid < GN) {
        int cwn = tid >> 5;
        int ci = tid & 31;
        float s = sS[cwn][0][ci] + sS[cwn][1][ci] + sS[cwn][2][ci] + sS[cwn][3][ci];
        float q = sQ[cwn][0][ci] + sQ[cwn][1][ci] + sQ[cwn][2][ci] + sQ[cwn][3][ci];
        d_ps[blockIdx.x][colBase + tid] = s;
        d_pq[blockIdx.x][colBase + tid] = q;
    }
}

// ---------------------------------------------------------------------------
// Kernel 3: finalize stats (in smem) + normalize + ReLU + dot(w2) -> logits.
// 128 blocks x 256 threads; each block: 32 rows (8 warps x 4 rows).
// ---------------------------------------------------------------------------
__global__ __launch_bounds__(256)
void logits_kernel(const float* __restrict__ gamma,
                   const float* __restrict__ beta,
                   const float* __restrict__ w2,
                   const float* __restrict__ b2,
                   float* __restrict__ out) {
    __shared__ float smu[Hn];
    __shared__ float sA[Hn];   // invstd * gamma

    int tid = threadIdx.x;
#pragma unroll
    for (int c = tid; c < Hn; c += 256) {
        float s = 0.f, sq = 0.f;
#pragma unroll
        for (int y = 0; y < 32; y++) { s += d_ps[y][c]; sq += d_pq[y][c]; }
        float mu = s * (1.0f / Bn);
        float var = sq * (1.0f / Bn) - mu * mu;
        smu[c] = mu;
        sA[c] = rsqrtf(var + EPS) * gamma[c];
    }
    __syncthreads();

    int warp = tid >> 5;
    int lane = tid & 31;
    float bias2 = b2[0];

#pragma unroll
    for (int r4 = 0; r4 < 4; r4++) {
        int row = blockIdx.x * 32 + warp * 4 + r4;
        const float4* zr = (const float4*)(d_z + (size_t)row * Hn);
        float sum = 0.f;
#pragma unroll
        for (int q = 0; q < 4; q++) {
            int c4 = lane + 32 * q;
            float4 z  = zr[c4];
            float4 mu = ((const float4*)smu)[c4];
            float4 a  = ((const float4*)sA)[c4];
            float4 be = ((const float4*)beta)[c4];
            float4 w  = ((const float4*)w2)[c4];
            sum += fmaxf((z.x - mu.x) * a.x + be.x, 0.f) * w.x;
            sum += fmaxf((z.y - mu.y) * a.y + be.y, 0.f) * w.y;
            sum += fmaxf((z.z - mu.z) * a.z + be.z, 0.f) * w.z;
            sum += fmaxf((z.w - mu.w) * a.w + be.w, 0.f) * w.w;
        }
#pragma unroll
        for (int o = 16; o > 0; o >>= 1) sum += __shfl_xor_sync(0xFFFFFFFFu, sum, o);
        if (lane == 0) out[1 + row] = sum + bias2;
    }
}

// ---------------------------------------------------------------------------
// Kernel 4: BCEWithLogits mean loss.
// ---------------------------------------------------------------------------
__global__ void loss_kernel(const float* __restrict__ t, float* __restrict__ out) {
    float acc = 0.f;
    for (int i = threadIdx.x; i < Bn; i += 1024) {
        float x = out[1 + i];
        float sp = fmaxf(x, 0.f) + log1pf(expf(-fabsf(x)));
        acc += sp - t[i] * x;
    }
    __shared__ float s[1024];
    s[threadIdx.x] = acc;
    __syncthreads();
    for (int st = 512; st > 0; st >>= 1) {
        if (threadIdx.x < st) s[threadIdx.x] += s[threadIdx.x + st];
        __syncthreads();
    }
    if (threadIdx.x == 0) out[0] = s[0] * (1.0f / Bn);
}

// ---------------------------------------------------------------------------
extern "C" void kernel_launch(void* const* d_in, const int* in_sizes, int n_in,
                              void* d_out, int out_size) {
    const int*   tokens = (const int*)d_in[0];
    const int*   seg    = (const int*)d_in[1];
    const float* t      = (const float*)d_in[2];
    const float* emb    = (const float*)d_in[3];
    const float* W1     = (const float*)d_in[4];
    const float* b1     = (const float*)d_in[5];
    const float* gamma  = (const float*)d_in[6];
    const float* beta   = (const float*)d_in[7];
    const float* w2     = (const float*)d_in[8];
    const float* b2     = (const float*)d_in[9];
    float* out = (float*)d_out;

    bounds_kernel<<<(Tn + 255) / 256, 256>>>(seg);
    bag_kernel<<<Bn, 128>>>(tokens, emb);
    gemm_kernel<<<dim3(Bn / GM, Hn / GN), 256>>>(W1, b1);
    logits_kernel<<<128, 256>>>(gamma, beta, w2, b2, out);
    loss_kernel<<<1, 1024>>>(t, out);
}